// round 12
// baseline (speedup 1.0000x reference)
#include <cuda_runtime.h>

// ---------------- problem constants ----------------
#define N_NODES   500000
#define F_DIM     128
#define E_EDGES   4000000
#define B_GRAPHS  4
#define GRID_G    32
#define V_SEG     (B_GRAPHS * GRID_G * GRID_G * GRID_G)   // 131072
#define INV_VOXEL 0.125f
#define INV_2R    0.0625f    // 1 / (2 * EFFECTIVE_RADIUS) = 1/16

// output layout (float32 elements)
#define OFF_PX    0
#define OFF_PPOS  (V_SEG * F_DIM)                          // 16,777,216
#define OFF_EI    (OFF_PPOS + V_SEG * 3)                   // 17,170,432
#define OFF_ATTR  (OFF_EI + 2 * E_EDGES)                   // 25,170,432
#define OFF_MASK  (OFF_ATTR + 3 * E_EDGES)                 // 37,170,432

// fat-kernel geometry
#define VOX_BLOCKS   (V_SEG * 32 / 256)           // 16384
#define EDGE_BLOCKS  ((E_EDGES / 4 + 255) / 256)  // 3907
#define GROUPS       (VOX_BLOCKS / 4)             // 4096  (>= EDGE_BLOCKS)
#define FAT_BLOCKS   (GROUPS * 5)                 // 20480

#define NODE_THREADS (N_NODES / 4)                // 125000
#define SCAT_THREADS (N_NODES / 2)                // 250000

#define FULLMASK 0xffffffffu

// ---------------- device scratch (zero at module load; k_alloc re-zeros
//                  accumulators each invocation after consuming them) -----
__device__ int    g_vid[N_NODES];
__device__ int    g_rank[N_NODES];
__device__ int    g_order[N_NODES];
__device__ float  g_possum[V_SEG * 3];
__device__ int    g_cnt[V_SEG];
__device__ int2   g_meta[V_SEG];       // (cnt, off) per voxel
__device__ float4 g_ppos4[V_SEG];
__device__ int    g_total;
__device__ int    g_ei_is64;

// ---------------- kernel 1: per-node vid/rank/count/pos-sums, 4 nodes/thr
//                  (+ dtype detect in block 0) ----------------------------
__global__ void k_node(const float4* __restrict__ pos4,
                       const int4* __restrict__ batch4,
                       const int* __restrict__ ei32) {
    if (blockIdx.x == 0) {
        unsigned any = 0;
        #pragma unroll 4
        for (int k = threadIdx.x; k < 1024; k += 256)
            any |= (unsigned)ei32[2 * k + 1];
        __shared__ unsigned s_any;
        if (threadIdx.x == 0) s_any = 0;
        __syncthreads();
        if (any) atomicOr(&s_any, 1u);
        __syncthreads();
        if (threadIdx.x == 0) g_ei_is64 = (s_any == 0) ? 1 : 0;
    }
    int t = blockIdx.x * blockDim.x + threadIdx.x;
    if (t >= NODE_THREADS) return;
    float4 A = pos4[3 * t + 0];
    float4 B = pos4[3 * t + 1];
    float4 C = pos4[3 * t + 2];
    int4 bb = batch4[t];

    float px[4] = {A.x, A.w, B.z, C.y};
    float py[4] = {A.y, B.x, B.w, C.z};
    float pz[4] = {A.z, B.y, C.x, C.w};
    int bv[4] = {bb.x, bb.y, bb.z, bb.w};

    int vv[4], rr[4];
    #pragma unroll
    for (int j = 0; j < 4; j++) {
        int vx = min(max((int)floorf(px[j] * INV_VOXEL), 0), GRID_G - 1);
        int vy = min(max((int)floorf(py[j] * INV_VOXEL), 0), GRID_G - 1);
        int vz = min(max((int)floorf(pz[j] * INV_VOXEL), 0), GRID_G - 1);
        int v = bv[j] * (GRID_G * GRID_G * GRID_G)
              + vx * (GRID_G * GRID_G) + vy * GRID_G + vz;
        vv[j] = v;
        rr[j] = atomicAdd(&g_cnt[v], 1);
        atomicAdd(&g_possum[v * 3 + 0], px[j]);
        atomicAdd(&g_possum[v * 3 + 1], py[j]);
        atomicAdd(&g_possum[v * 3 + 2], pz[j]);
    }
    ((int4*)g_vid)[t]  = make_int4(vv[0], vv[1], vv[2], vv[3]);
    ((int4*)g_rank)[t] = make_int4(rr[0], rr[1], rr[2], rr[3]);
}

// ---------------- fused: segment offsets (block scan + global cursor)
//        + pooled_pos finalize + accumulator re-zero for next launch ------
__global__ void k_alloc(float* __restrict__ out_f) {
    int v = blockIdx.x * 256 + threadIdx.x;
    int lane = threadIdx.x & 31;
    int wid = threadIdx.x >> 5;
    int cnt = g_cnt[v];

    int val = cnt;
    #pragma unroll
    for (int d = 1; d < 32; d <<= 1) {
        int t = __shfl_up_sync(FULLMASK, val, d);
        if (lane >= d) val += t;
    }
    __shared__ int wsum[8];
    __shared__ int s_base;
    if (lane == 31) wsum[wid] = val;
    __syncthreads();
    if (threadIdx.x < 8) {
        int w = wsum[threadIdx.x];
        #pragma unroll
        for (int d = 1; d < 8; d <<= 1) {
            int t = __shfl_up_sync(0xff, w, d);
            if (threadIdx.x >= d) w += t;
        }
        wsum[threadIdx.x] = w;
        if (threadIdx.x == 7) s_base = atomicAdd(&g_total, w);
    }
    __syncthreads();
    int off = s_base + (val - cnt) + (wid > 0 ? wsum[wid - 1] : 0);
    g_meta[v] = make_int2(cnt, off);

    float inv = 1.0f / fmaxf((float)cnt, 1.0f);
    float px = g_possum[v * 3 + 0] * inv;
    float py = g_possum[v * 3 + 1] * inv;
    float pz = g_possum[v * 3 + 2] * inv;
    out_f[OFF_PPOS + v * 3 + 0] = px;
    out_f[OFF_PPOS + v * 3 + 1] = py;
    out_f[OFF_PPOS + v * 3 + 2] = pz;
    g_ppos4[v] = make_float4(px, py, pz, 0.0f);

    // re-zero accumulators for the next kernel_launch invocation
    g_cnt[v] = 0;
    g_possum[v * 3 + 0] = 0.0f;
    g_possum[v * 3 + 1] = 0.0f;
    g_possum[v * 3 + 2] = 0.0f;
}

// ---------------- scatter: atomic-free counting sort, 2 nodes/thread ------
__global__ void k_scatter() {
    int t = blockIdx.x * blockDim.x + threadIdx.x;
    if (t >= SCAT_THREADS) return;
    int2 v2 = ((const int2*)g_vid)[t];
    int2 r2 = ((const int2*)g_rank)[t];
    int n = t * 2;
    g_order[g_meta[v2.x].y + r2.x] = n;
    g_order[g_meta[v2.y].y + r2.y] = n + 1;
}

// ---------------- voxmax block body ----------------
// node-id list fetched once lane-parallel, broadcast via shfl (no L1 traffic
// for ids inside the loop). Fallback load path for cnt > 32.
__device__ __forceinline__ void vox_body(int vb, const float4* __restrict__ x4,
                                         float4* __restrict__ out4) {
    int t = vb * 256 + threadIdx.x;
    int w = t >> 5;
    int lane = t & 31;
    int2 meta = g_meta[w];
    int cnt = meta.x;
    float4 acc = make_float4(0.f, 0.f, 0.f, 0.f);
    if (cnt > 0) {
        const float NEG = -3.402823466e38f;
        acc = make_float4(NEG, NEG, NEG, NEG);
        int off = meta.y;
        bool small = (cnt <= 32);
        int myid = 0;
        if (small) myid = g_order[off + min(lane, cnt - 1)];  // 1 coalesced LDG

        #define GETID(idx) (small ? __shfl_sync(FULLMASK, myid, (idx)) \
                                  : g_order[off + (idx)])
        int i = 0;
        for (; i + 4 <= cnt; i += 4) {
            int n0 = GETID(i + 0);
            int n1 = GETID(i + 1);
            int n2 = GETID(i + 2);
            int n3 = GETID(i + 3);
            float4 a = __ldcs(&x4[(size_t)n0 * 32 + lane]);
            float4 b = __ldcs(&x4[(size_t)n1 * 32 + lane]);
            float4 c = __ldcs(&x4[(size_t)n2 * 32 + lane]);
            float4 d = __ldcs(&x4[(size_t)n3 * 32 + lane]);
            acc.x = fmaxf(acc.x, fmaxf(fmaxf(a.x, b.x), fmaxf(c.x, d.x)));
            acc.y = fmaxf(acc.y, fmaxf(fmaxf(a.y, b.y), fmaxf(c.y, d.y)));
            acc.z = fmaxf(acc.z, fmaxf(fmaxf(a.z, b.z), fmaxf(c.z, d.z)));
            acc.w = fmaxf(acc.w, fmaxf(fmaxf(a.w, b.w), fmaxf(c.w, d.w)));
        }
        int rem = cnt - i;
        if (rem == 3) {
            int n0 = GETID(i + 0);
            int n1 = GETID(i + 1);
            int n2 = GETID(i + 2);
            float4 a = __ldcs(&x4[(size_t)n0 * 32 + lane]);
            float4 b = __ldcs(&x4[(size_t)n1 * 32 + lane]);
            float4 c = __ldcs(&x4[(size_t)n2 * 32 + lane]);
            acc.x = fmaxf(acc.x, fmaxf(fmaxf(a.x, b.x), c.x));
            acc.y = fmaxf(acc.y, fmaxf(fmaxf(a.y, b.y), c.y));
            acc.z = fmaxf(acc.z, fmaxf(fmaxf(a.z, b.z), c.z));
            acc.w = fmaxf(acc.w, fmaxf(fmaxf(a.w, b.w), c.w));
        } else if (rem == 2) {
            int n0 = GETID(i + 0);
            int n1 = GETID(i + 1);
            float4 a = __ldcs(&x4[(size_t)n0 * 32 + lane]);
            float4 b = __ldcs(&x4[(size_t)n1 * 32 + lane]);
            acc.x = fmaxf(acc.x, fmaxf(a.x, b.x));
            acc.y = fmaxf(acc.y, fmaxf(a.y, b.y));
            acc.z = fmaxf(acc.z, fmaxf(a.z, b.z));
            acc.w = fmaxf(acc.w, fmaxf(a.w, b.w));
        } else if (rem == 1) {
            int n0 = GETID(i);
            float4 a = __ldcs(&x4[(size_t)n0 * 32 + lane]);
            acc.x = fmaxf(acc.x, a.x);
            acc.y = fmaxf(acc.y, a.y);
            acc.z = fmaxf(acc.z, a.z);
            acc.w = fmaxf(acc.w, a.w);
        }
        #undef GETID
    }
    __stcs(&out4[(size_t)w * 32 + lane], acc);
}

// ---------------- edge attr helper: one edge pair -> 6 floats ----------
__device__ __forceinline__ void edge_attr_pair(int vsA, int vdA, bool mA,
                                               int vsB, int vdB, bool mB,
                                               float* o /*6 floats*/) {
    float4 psA = g_ppos4[vsA], pdA = g_ppos4[vdA];
    float4 psB = g_ppos4[vsB], pdB = g_ppos4[vdB];
    o[0] = mA ? (pdA.x - psA.x) * INV_2R + 0.5f : 0.f;
    o[1] = mA ? (pdA.y - psA.y) * INV_2R + 0.5f : 0.f;
    o[2] = mA ? (pdA.z - psA.z) * INV_2R + 0.5f : 0.f;
    o[3] = mB ? (pdB.x - psB.x) * INV_2R + 0.5f : 0.f;
    o[4] = mB ? (pdB.y - psB.y) * INV_2R + 0.5f : 0.f;
    o[5] = mB ? (pdB.z - psB.z) * INV_2R + 0.5f : 0.f;
}

// ---------------- edge block body: 4 edges per thread ----------------
__device__ __forceinline__ void edge_body(int eb, const void* __restrict__ ei_raw,
                                          float* __restrict__ out_f) {
    int t = eb * 256 + threadIdx.x;
    if (t >= E_EDGES / 4) return;

    int s0, s1, s2, s3, d0, d1, d2, d3;
    if (g_ei_is64) {
        const longlong2* p = (const longlong2*)ei_raw;
        longlong2 a = __ldcs(&p[2 * t]);
        longlong2 b = __ldcs(&p[2 * t + 1]);
        longlong2 c = __ldcs(&p[E_EDGES / 2 + 2 * t]);
        longlong2 d = __ldcs(&p[E_EDGES / 2 + 2 * t + 1]);
        s0 = (int)a.x; s1 = (int)a.y; s2 = (int)b.x; s3 = (int)b.y;
        d0 = (int)c.x; d1 = (int)c.y; d2 = (int)d.x; d3 = (int)d.y;
    } else {
        const int4* p = (const int4*)ei_raw;
        int4 a = __ldcs(&p[t]);
        int4 b = __ldcs(&p[E_EDGES / 4 + t]);
        s0 = a.x; s1 = a.y; s2 = a.z; s3 = a.w;
        d0 = b.x; d1 = b.y; d2 = b.z; d3 = b.w;
    }
    s0 = min(max(s0, 0), N_NODES - 1);
    s1 = min(max(s1, 0), N_NODES - 1);
    s2 = min(max(s2, 0), N_NODES - 1);
    s3 = min(max(s3, 0), N_NODES - 1);
    d0 = min(max(d0, 0), N_NODES - 1);
    d1 = min(max(d1, 0), N_NODES - 1);
    d2 = min(max(d2, 0), N_NODES - 1);
    d3 = min(max(d3, 0), N_NODES - 1);

    int vs0 = g_vid[s0], vs1 = g_vid[s1], vs2 = g_vid[s2], vs3 = g_vid[s3];
    int vd0 = g_vid[d0], vd1 = g_vid[d1], vd2 = g_vid[d2], vd3 = g_vid[d3];
    bool m0 = vs0 != vd0, m1 = vs1 != vd1, m2 = vs2 != vd2, m3 = vs3 != vd3;

    __stcs(&((float4*)(out_f + OFF_EI))[t],
           make_float4((float)vs0, (float)vs1, (float)vs2, (float)vs3));
    __stcs(&((float4*)(out_f + OFF_EI + E_EDGES))[t],
           make_float4((float)vd0, (float)vd1, (float)vd2, (float)vd3));
    __stcs(&((float4*)(out_f + OFF_MASK))[t],
           make_float4(m0 ? 1.f : 0.f, m1 ? 1.f : 0.f, m2 ? 1.f : 0.f, m3 ? 1.f : 0.f));

    float o[12];
    edge_attr_pair(vs0, vd0, m0, vs1, vd1, m1, o);
    edge_attr_pair(vs2, vd2, m2, vs3, vd3, m3, o + 6);

    float4* attr = (float4*)(out_f + OFF_ATTR + (size_t)t * 12);
    __stcs(&attr[0], make_float4(o[0], o[1], o[2], o[3]));
    __stcs(&attr[1], make_float4(o[4], o[5], o[6], o[7]));
    __stcs(&attr[2], make_float4(o[8], o[9], o[10], o[11]));
}

// ---------------- fat kernel: interleaved voxmax + edge blocks ----------------
__global__ void __launch_bounds__(256, 8)
k_voxedge(const float4* __restrict__ x4,
          const void* __restrict__ ei_raw,
          float* __restrict__ out_f) {
    if (blockIdx.x == 0 && threadIdx.x == 0) g_total = 0;  // reset for next launch
    int g = blockIdx.x / 5;
    int r = blockIdx.x % 5;
    if (r < 4) {
        vox_body(g * 4 + r, x4, (float4*)out_f);
    } else {
        if (g < EDGE_BLOCKS) edge_body(g, ei_raw, out_f);
    }
}

// ---------------- launch ----------------
extern "C" void kernel_launch(void* const* d_in, const int* in_sizes, int n_in,
                              void* d_out, int out_size) {
    const float* x = nullptr;
    const float* pos = nullptr;
    const int* batch = nullptr;
    const void* ei = nullptr;
    for (int i = 0; i < n_in; i++) {
        switch (in_sizes[i]) {
            case 64000000: x     = (const float*)d_in[i]; break;  // [N,F]
            case 1500000:  pos   = (const float*)d_in[i]; break;  // [N,3]
            case 500000:   batch = (const int*)d_in[i];   break;  // [N]
            case 8000000:  ei    = d_in[i];                break;  // [2,E]
        }
    }
    float* out = (float*)d_out;

    const int T = 256;
    k_node<<<(NODE_THREADS + T - 1) / T, T>>>((const float4*)pos,
                                              (const int4*)batch,
                                              (const int*)ei);
    k_alloc<<<V_SEG / 256, 256>>>(out);
    k_scatter<<<(SCAT_THREADS + T - 1) / T, T>>>();
    k_voxedge<<<FAT_BLOCKS, T>>>((const float4*)x, ei, out);
}

// round 13
// speedup vs baseline: 1.1202x; 1.1202x over previous
#include <cuda_runtime.h>

// ---------------- problem constants ----------------
#define N_NODES   500000
#define F_DIM     128
#define E_EDGES   4000000
#define B_GRAPHS  4
#define GRID_G    32
#define V_SEG     (B_GRAPHS * GRID_G * GRID_G * GRID_G)   // 131072
#define INV_VOXEL 0.125f
#define INV_2R    0.0625f    // 1 / (2 * EFFECTIVE_RADIUS) = 1/16

// output layout (float32 elements)
#define OFF_PX    0
#define OFF_PPOS  (V_SEG * F_DIM)                          // 16,777,216
#define OFF_EI    (OFF_PPOS + V_SEG * 3)                   // 17,170,432
#define OFF_ATTR  (OFF_EI + 2 * E_EDGES)                   // 25,170,432
#define OFF_MASK  (OFF_ATTR + 3 * E_EDGES)                 // 37,170,432

// fat-kernel geometry
#define VOX_BLOCKS   (V_SEG * 32 / 256)           // 16384
#define EDGE_BLOCKS  ((E_EDGES / 4 + 255) / 256)  // 3907
#define GROUPS       (VOX_BLOCKS / 4)             // 4096  (>= EDGE_BLOCKS)
#define FAT_BLOCKS   (GROUPS * 5)                 // 20480

#define NODE_THREADS (N_NODES / 4)                // 125000
#define SCAT_THREADS (N_NODES / 2)                // 250000

#define FULLMASK 0xffffffffu

// ---------------- device scratch (zero at module load; k_alloc re-zeros
//                  accumulators each invocation after consuming them) -----
__device__ int    g_vid[N_NODES];
__device__ int    g_rank[N_NODES];
__device__ int    g_order[N_NODES];
__device__ float4 g_ninfo[N_NODES];    // (ppos.x, ppos.y, ppos.z, (float)vid)
__device__ float  g_possum[V_SEG * 3];
__device__ int    g_cnt[V_SEG];
__device__ int2   g_meta[V_SEG];       // (cnt, off) per voxel
__device__ float4 g_ppos4[V_SEG];
__device__ int    g_total;
__device__ int    g_ei_is64;

// ---------------- kernel 1: per-node vid/rank/count/pos-sums, 4 nodes/thr
//                  (+ dtype detect in block 0) ----------------------------
__global__ void k_node(const float4* __restrict__ pos4,
                       const int4* __restrict__ batch4,
                       const int* __restrict__ ei32) {
    if (blockIdx.x == 0) {
        unsigned any = 0;
        #pragma unroll 4
        for (int k = threadIdx.x; k < 1024; k += 256)
            any |= (unsigned)ei32[2 * k + 1];
        __shared__ unsigned s_any;
        if (threadIdx.x == 0) s_any = 0;
        __syncthreads();
        if (any) atomicOr(&s_any, 1u);
        __syncthreads();
        if (threadIdx.x == 0) g_ei_is64 = (s_any == 0) ? 1 : 0;
    }
    int t = blockIdx.x * blockDim.x + threadIdx.x;
    if (t >= NODE_THREADS) return;
    float4 A = pos4[3 * t + 0];
    float4 B = pos4[3 * t + 1];
    float4 C = pos4[3 * t + 2];
    int4 bb = batch4[t];

    float px[4] = {A.x, A.w, B.z, C.y};
    float py[4] = {A.y, B.x, B.w, C.z};
    float pz[4] = {A.z, B.y, C.x, C.w};
    int bv[4] = {bb.x, bb.y, bb.z, bb.w};

    int vv[4], rr[4];
    #pragma unroll
    for (int j = 0; j < 4; j++) {
        int vx = min(max((int)floorf(px[j] * INV_VOXEL), 0), GRID_G - 1);
        int vy = min(max((int)floorf(py[j] * INV_VOXEL), 0), GRID_G - 1);
        int vz = min(max((int)floorf(pz[j] * INV_VOXEL), 0), GRID_G - 1);
        int v = bv[j] * (GRID_G * GRID_G * GRID_G)
              + vx * (GRID_G * GRID_G) + vy * GRID_G + vz;
        vv[j] = v;
        rr[j] = atomicAdd(&g_cnt[v], 1);
        atomicAdd(&g_possum[v * 3 + 0], px[j]);
        atomicAdd(&g_possum[v * 3 + 1], py[j]);
        atomicAdd(&g_possum[v * 3 + 2], pz[j]);
    }
    ((int4*)g_vid)[t]  = make_int4(vv[0], vv[1], vv[2], vv[3]);
    ((int4*)g_rank)[t] = make_int4(rr[0], rr[1], rr[2], rr[3]);
}

// ---------------- fused: segment offsets (block scan + global cursor)
//        + pooled_pos finalize + accumulator re-zero for next launch ------
__global__ void k_alloc(float* __restrict__ out_f) {
    int v = blockIdx.x * 256 + threadIdx.x;
    int lane = threadIdx.x & 31;
    int wid = threadIdx.x >> 5;
    int cnt = g_cnt[v];

    int val = cnt;
    #pragma unroll
    for (int d = 1; d < 32; d <<= 1) {
        int t = __shfl_up_sync(FULLMASK, val, d);
        if (lane >= d) val += t;
    }
    __shared__ int wsum[8];
    __shared__ int s_base;
    if (lane == 31) wsum[wid] = val;
    __syncthreads();
    if (threadIdx.x < 8) {
        int w = wsum[threadIdx.x];
        #pragma unroll
        for (int d = 1; d < 8; d <<= 1) {
            int t = __shfl_up_sync(0xff, w, d);
            if (threadIdx.x >= d) w += t;
        }
        wsum[threadIdx.x] = w;
        if (threadIdx.x == 7) s_base = atomicAdd(&g_total, w);
    }
    __syncthreads();
    int off = s_base + (val - cnt) + (wid > 0 ? wsum[wid - 1] : 0);
    g_meta[v] = make_int2(cnt, off);

    float inv = 1.0f / fmaxf((float)cnt, 1.0f);
    float px = g_possum[v * 3 + 0] * inv;
    float py = g_possum[v * 3 + 1] * inv;
    float pz = g_possum[v * 3 + 2] * inv;
    out_f[OFF_PPOS + v * 3 + 0] = px;
    out_f[OFF_PPOS + v * 3 + 1] = py;
    out_f[OFF_PPOS + v * 3 + 2] = pz;
    g_ppos4[v] = make_float4(px, py, pz, 0.0f);

    // re-zero accumulators for the next kernel_launch invocation
    g_cnt[v] = 0;
    g_possum[v * 3 + 0] = 0.0f;
    g_possum[v * 3 + 1] = 0.0f;
    g_possum[v * 3 + 2] = 0.0f;
}

// ---------------- scatter: counting sort + combined node-info table -------
__global__ void k_scatter() {
    int t = blockIdx.x * blockDim.x + threadIdx.x;
    if (t >= SCAT_THREADS) return;
    int2 v2 = ((const int2*)g_vid)[t];
    int2 r2 = ((const int2*)g_rank)[t];
    int n = t * 2;
    g_order[g_meta[v2.x].y + r2.x] = n;
    g_order[g_meta[v2.y].y + r2.y] = n + 1;
    // combined (ppos, vid) table, node-indexed, coalesced store
    float4 p0 = g_ppos4[v2.x];
    float4 p1 = g_ppos4[v2.y];
    p0.w = (float)v2.x;
    p1.w = (float)v2.y;
    g_ninfo[n]     = p0;
    g_ninfo[n + 1] = p1;
}

// ---------------- voxmax block body (R11 direct-load version) -------------
__device__ __forceinline__ void vox_body(int vb, const float4* __restrict__ x4,
                                         float4* __restrict__ out4) {
    int t = vb * 256 + threadIdx.x;
    int w = t >> 5;
    int lane = t & 31;
    int2 meta = g_meta[w];
    int cnt = meta.x;
    float4 acc = make_float4(0.f, 0.f, 0.f, 0.f);
    if (cnt > 0) {
        const float NEG = -3.402823466e38f;
        acc = make_float4(NEG, NEG, NEG, NEG);
        int off = meta.y;
        int i = 0;
        for (; i + 4 <= cnt; i += 4) {
            int n0 = g_order[off + i + 0];
            int n1 = g_order[off + i + 1];
            int n2 = g_order[off + i + 2];
            int n3 = g_order[off + i + 3];
            float4 a = __ldcs(&x4[(size_t)n0 * 32 + lane]);
            float4 b = __ldcs(&x4[(size_t)n1 * 32 + lane]);
            float4 c = __ldcs(&x4[(size_t)n2 * 32 + lane]);
            float4 d = __ldcs(&x4[(size_t)n3 * 32 + lane]);
            acc.x = fmaxf(acc.x, fmaxf(fmaxf(a.x, b.x), fmaxf(c.x, d.x)));
            acc.y = fmaxf(acc.y, fmaxf(fmaxf(a.y, b.y), fmaxf(c.y, d.y)));
            acc.z = fmaxf(acc.z, fmaxf(fmaxf(a.z, b.z), fmaxf(c.z, d.z)));
            acc.w = fmaxf(acc.w, fmaxf(fmaxf(a.w, b.w), fmaxf(c.w, d.w)));
        }
        int rem = cnt - i;
        if (rem == 3) {
            int n0 = g_order[off + i + 0];
            int n1 = g_order[off + i + 1];
            int n2 = g_order[off + i + 2];
            float4 a = __ldcs(&x4[(size_t)n0 * 32 + lane]);
            float4 b = __ldcs(&x4[(size_t)n1 * 32 + lane]);
            float4 c = __ldcs(&x4[(size_t)n2 * 32 + lane]);
            acc.x = fmaxf(acc.x, fmaxf(fmaxf(a.x, b.x), c.x));
            acc.y = fmaxf(acc.y, fmaxf(fmaxf(a.y, b.y), c.y));
            acc.z = fmaxf(acc.z, fmaxf(fmaxf(a.z, b.z), c.z));
            acc.w = fmaxf(acc.w, fmaxf(fmaxf(a.w, b.w), c.w));
        } else if (rem == 2) {
            int n0 = g_order[off + i + 0];
            int n1 = g_order[off + i + 1];
            float4 a = __ldcs(&x4[(size_t)n0 * 32 + lane]);
            float4 b = __ldcs(&x4[(size_t)n1 * 32 + lane]);
            acc.x = fmaxf(acc.x, fmaxf(a.x, b.x));
            acc.y = fmaxf(acc.y, fmaxf(a.y, b.y));
            acc.z = fmaxf(acc.z, fmaxf(a.z, b.z));
            acc.w = fmaxf(acc.w, fmaxf(a.w, b.w));
        } else if (rem == 1) {
            int n0 = g_order[off + i];
            float4 a = __ldcs(&x4[(size_t)n0 * 32 + lane]);
            acc.x = fmaxf(acc.x, a.x);
            acc.y = fmaxf(acc.y, a.y);
            acc.z = fmaxf(acc.z, a.z);
            acc.w = fmaxf(acc.w, a.w);
        }
    }
    __stcs(&out4[(size_t)w * 32 + lane], acc);
}

// ---------------- edge block body: 4 edges/thread, 1-level gathers --------
__device__ __forceinline__ void edge_body(int eb, const void* __restrict__ ei_raw,
                                          float* __restrict__ out_f) {
    int t = eb * 256 + threadIdx.x;
    if (t >= E_EDGES / 4) return;

    int s0, s1, s2, s3, d0, d1, d2, d3;
    if (g_ei_is64) {
        const longlong2* p = (const longlong2*)ei_raw;
        longlong2 a = __ldcs(&p[2 * t]);
        longlong2 b = __ldcs(&p[2 * t + 1]);
        longlong2 c = __ldcs(&p[E_EDGES / 2 + 2 * t]);
        longlong2 d = __ldcs(&p[E_EDGES / 2 + 2 * t + 1]);
        s0 = (int)a.x; s1 = (int)a.y; s2 = (int)b.x; s3 = (int)b.y;
        d0 = (int)c.x; d1 = (int)c.y; d2 = (int)d.x; d3 = (int)d.y;
    } else {
        const int4* p = (const int4*)ei_raw;
        int4 a = __ldcs(&p[t]);
        int4 b = __ldcs(&p[E_EDGES / 4 + t]);
        s0 = a.x; s1 = a.y; s2 = a.z; s3 = a.w;
        d0 = b.x; d1 = b.y; d2 = b.z; d3 = b.w;
    }
    s0 = min(max(s0, 0), N_NODES - 1);
    s1 = min(max(s1, 0), N_NODES - 1);
    s2 = min(max(s2, 0), N_NODES - 1);
    s3 = min(max(s3, 0), N_NODES - 1);
    d0 = min(max(d0, 0), N_NODES - 1);
    d1 = min(max(d1, 0), N_NODES - 1);
    d2 = min(max(d2, 0), N_NODES - 1);
    d3 = min(max(d3, 0), N_NODES - 1);

    float o[12];
    float vsf[4], vdf[4], mk[4];

    // phase A: edges 0,1
    {
        float4 S0 = g_ninfo[s0], D0 = g_ninfo[d0];
        float4 S1 = g_ninfo[s1], D1 = g_ninfo[d1];
        bool m0 = S0.w != D0.w;
        bool m1 = S1.w != D1.w;
        vsf[0] = S0.w; vdf[0] = D0.w; mk[0] = m0 ? 1.f : 0.f;
        vsf[1] = S1.w; vdf[1] = D1.w; mk[1] = m1 ? 1.f : 0.f;
        o[0] = m0 ? (D0.x - S0.x) * INV_2R + 0.5f : 0.f;
        o[1] = m0 ? (D0.y - S0.y) * INV_2R + 0.5f : 0.f;
        o[2] = m0 ? (D0.z - S0.z) * INV_2R + 0.5f : 0.f;
        o[3] = m1 ? (D1.x - S1.x) * INV_2R + 0.5f : 0.f;
        o[4] = m1 ? (D1.y - S1.y) * INV_2R + 0.5f : 0.f;
        o[5] = m1 ? (D1.z - S1.z) * INV_2R + 0.5f : 0.f;
    }
    // phase B: edges 2,3
    {
        float4 S2 = g_ninfo[s2], D2 = g_ninfo[d2];
        float4 S3 = g_ninfo[s3], D3 = g_ninfo[d3];
        bool m2 = S2.w != D2.w;
        bool m3 = S3.w != D3.w;
        vsf[2] = S2.w; vdf[2] = D2.w; mk[2] = m2 ? 1.f : 0.f;
        vsf[3] = S3.w; vdf[3] = D3.w; mk[3] = m3 ? 1.f : 0.f;
        o[6]  = m2 ? (D2.x - S2.x) * INV_2R + 0.5f : 0.f;
        o[7]  = m2 ? (D2.y - S2.y) * INV_2R + 0.5f : 0.f;
        o[8]  = m2 ? (D2.z - S2.z) * INV_2R + 0.5f : 0.f;
        o[9]  = m3 ? (D3.x - S3.x) * INV_2R + 0.5f : 0.f;
        o[10] = m3 ? (D3.y - S3.y) * INV_2R + 0.5f : 0.f;
        o[11] = m3 ? (D3.z - S3.z) * INV_2R + 0.5f : 0.f;
    }

    __stcs(&((float4*)(out_f + OFF_EI))[t],
           make_float4(vsf[0], vsf[1], vsf[2], vsf[3]));
    __stcs(&((float4*)(out_f + OFF_EI + E_EDGES))[t],
           make_float4(vdf[0], vdf[1], vdf[2], vdf[3]));
    __stcs(&((float4*)(out_f + OFF_MASK))[t],
           make_float4(mk[0], mk[1], mk[2], mk[3]));

    float4* attr = (float4*)(out_f + OFF_ATTR + (size_t)t * 12);
    __stcs(&attr[0], make_float4(o[0], o[1], o[2], o[3]));
    __stcs(&attr[1], make_float4(o[4], o[5], o[6], o[7]));
    __stcs(&attr[2], make_float4(o[8], o[9], o[10], o[11]));
}

// ---------------- fat kernel: interleaved voxmax + edge blocks ----------------
__global__ void __launch_bounds__(256, 8)
k_voxedge(const float4* __restrict__ x4,
          const void* __restrict__ ei_raw,
          float* __restrict__ out_f) {
    if (blockIdx.x == 0 && threadIdx.x == 0) g_total = 0;  // reset for next launch
    int g = blockIdx.x / 5;
    int r = blockIdx.x % 5;
    if (r < 4) {
        vox_body(g * 4 + r, x4, (float4*)out_f);
    } else {
        if (g < EDGE_BLOCKS) edge_body(g, ei_raw, out_f);
    }
}

// ---------------- launch ----------------
extern "C" void kernel_launch(void* const* d_in, const int* in_sizes, int n_in,
                              void* d_out, int out_size) {
    const float* x = nullptr;
    const float* pos = nullptr;
    const int* batch = nullptr;
    const void* ei = nullptr;
    for (int i = 0; i < n_in; i++) {
        switch (in_sizes[i]) {
            case 64000000: x     = (const float*)d_in[i]; break;  // [N,F]
            case 1500000:  pos   = (const float*)d_in[i]; break;  // [N,3]
            case 500000:   batch = (const int*)d_in[i];   break;  // [N]
            case 8000000:  ei    = d_in[i];                break;  // [2,E]
        }
    }
    float* out = (float*)d_out;

    const int T = 256;
    k_node<<<(NODE_THREADS + T - 1) / T, T>>>((const float4*)pos,
                                              (const int4*)batch,
                                              (const int*)ei);
    k_alloc<<<V_SEG / 256, 256>>>(out);
    k_scatter<<<(SCAT_THREADS + T - 1) / T, T>>>();
    k_voxedge<<<FAT_BLOCKS, T>>>((const float4*)x, ei, out);
}

// round 14
// speedup vs baseline: 1.1377x; 1.0156x over previous
#include <cuda_runtime.h>

// ---------------- problem constants ----------------
#define N_NODES   500000
#define F_DIM     128
#define E_EDGES   4000000
#define B_GRAPHS  4
#define GRID_G    32
#define V_SEG     (B_GRAPHS * GRID_G * GRID_G * GRID_G)   // 131072
#define INV_VOXEL 0.125f
#define INV_2R    0.0625f    // 1 / (2 * EFFECTIVE_RADIUS) = 1/16

// output layout (float32 elements)
#define OFF_PX    0
#define OFF_PPOS  (V_SEG * F_DIM)                          // 16,777,216
#define OFF_EI    (OFF_PPOS + V_SEG * 3)                   // 17,170,432
#define OFF_ATTR  (OFF_EI + 2 * E_EDGES)                   // 25,170,432
#define OFF_MASK  (OFF_ATTR + 3 * E_EDGES)                 // 37,170,432

// fat-kernel geometry
#define VOX_BLOCKS   (V_SEG * 32 / 256)           // 16384
#define EDGE_BLOCKS  ((E_EDGES / 4 + 255) / 256)  // 3907
#define GROUPS       (VOX_BLOCKS / 4)             // 4096  (>= EDGE_BLOCKS)
#define FAT_BLOCKS   (GROUPS * 5)                 // 20480

#define NODE_THREADS (N_NODES / 4)                // 125000
#define SCAT_THREADS (N_NODES / 2)                // 250000

#define FULLMASK 0xffffffffu
#define VR_SHIFT 17                               // vid in [0,2^17), rank above

// ---------------- device scratch (zero at module load; k_alloc re-zeros
//                  accumulators each invocation after consuming them) -----
__device__ int    g_vr[N_NODES];       // packed: vid | (rank << VR_SHIFT)
__device__ int    g_order[N_NODES];
__device__ float4 g_ninfo[N_NODES];    // (ppos.x, ppos.y, ppos.z, (float)vid)
__device__ float  g_possum[V_SEG * 3];
__device__ int    g_cnt[V_SEG];
__device__ int2   g_meta[V_SEG];       // (cnt, off) per voxel
__device__ float4 g_ppos4[V_SEG];
__device__ int    g_total;
__device__ int    g_ei_is64;

// ---------------- kernel 1: per-node vid/rank/count/pos-sums, 4 nodes/thr
//                  (+ dtype detect in block 0) ----------------------------
__global__ void k_node(const float4* __restrict__ pos4,
                       const int4* __restrict__ batch4,
                       const int* __restrict__ ei32) {
    if (blockIdx.x == 0) {
        unsigned any = 0;
        #pragma unroll 4
        for (int k = threadIdx.x; k < 1024; k += 256)
            any |= (unsigned)ei32[2 * k + 1];
        __shared__ unsigned s_any;
        if (threadIdx.x == 0) s_any = 0;
        __syncthreads();
        if (any) atomicOr(&s_any, 1u);
        __syncthreads();
        if (threadIdx.x == 0) g_ei_is64 = (s_any == 0) ? 1 : 0;
    }
    int t = blockIdx.x * blockDim.x + threadIdx.x;
    if (t >= NODE_THREADS) return;
    float4 A = pos4[3 * t + 0];
    float4 B = pos4[3 * t + 1];
    float4 C = pos4[3 * t + 2];
    int4 bb = batch4[t];

    float px[4] = {A.x, A.w, B.z, C.y};
    float py[4] = {A.y, B.x, B.w, C.z};
    float pz[4] = {A.z, B.y, C.x, C.w};
    int bv[4] = {bb.x, bb.y, bb.z, bb.w};

    int vr[4];
    #pragma unroll
    for (int j = 0; j < 4; j++) {
        int vx = min(max((int)floorf(px[j] * INV_VOXEL), 0), GRID_G - 1);
        int vy = min(max((int)floorf(py[j] * INV_VOXEL), 0), GRID_G - 1);
        int vz = min(max((int)floorf(pz[j] * INV_VOXEL), 0), GRID_G - 1);
        int v = bv[j] * (GRID_G * GRID_G * GRID_G)
              + vx * (GRID_G * GRID_G) + vy * GRID_G + vz;
        int r = atomicAdd(&g_cnt[v], 1);
        vr[j] = v | (r << VR_SHIFT);
        atomicAdd(&g_possum[v * 3 + 0], px[j]);
        atomicAdd(&g_possum[v * 3 + 1], py[j]);
        atomicAdd(&g_possum[v * 3 + 2], pz[j]);
    }
    ((int4*)g_vr)[t] = make_int4(vr[0], vr[1], vr[2], vr[3]);
}

// ---------------- fused: segment offsets (block scan + global cursor)
//        + pooled_pos finalize + accumulator re-zero for next launch ------
__global__ void k_alloc(float* __restrict__ out_f) {
    int v = blockIdx.x * 256 + threadIdx.x;
    int lane = threadIdx.x & 31;
    int wid = threadIdx.x >> 5;
    int cnt = g_cnt[v];

    int val = cnt;
    #pragma unroll
    for (int d = 1; d < 32; d <<= 1) {
        int t = __shfl_up_sync(FULLMASK, val, d);
        if (lane >= d) val += t;
    }
    __shared__ int wsum[8];
    __shared__ int s_base;
    if (lane == 31) wsum[wid] = val;
    __syncthreads();
    if (threadIdx.x < 8) {
        int w = wsum[threadIdx.x];
        #pragma unroll
        for (int d = 1; d < 8; d <<= 1) {
            int t = __shfl_up_sync(0xff, w, d);
            if (threadIdx.x >= d) w += t;
        }
        wsum[threadIdx.x] = w;
        if (threadIdx.x == 7) s_base = atomicAdd(&g_total, w);
    }
    __syncthreads();
    int off = s_base + (val - cnt) + (wid > 0 ? wsum[wid - 1] : 0);
    g_meta[v] = make_int2(cnt, off);

    float inv = 1.0f / fmaxf((float)cnt, 1.0f);
    float px = g_possum[v * 3 + 0] * inv;
    float py = g_possum[v * 3 + 1] * inv;
    float pz = g_possum[v * 3 + 2] * inv;
    out_f[OFF_PPOS + v * 3 + 0] = px;
    out_f[OFF_PPOS + v * 3 + 1] = py;
    out_f[OFF_PPOS + v * 3 + 2] = pz;
    g_ppos4[v] = make_float4(px, py, pz, 0.0f);

    // re-zero accumulators for the next kernel_launch invocation
    g_cnt[v] = 0;
    g_possum[v * 3 + 0] = 0.0f;
    g_possum[v * 3 + 1] = 0.0f;
    g_possum[v * 3 + 2] = 0.0f;
}

// ---------------- scatter: counting sort + combined node-info table -------
__global__ void k_scatter() {
    int t = blockIdx.x * blockDim.x + threadIdx.x;
    if (t >= SCAT_THREADS) return;
    int2 vr2 = ((const int2*)g_vr)[t];
    int v0 = vr2.x & ((1 << VR_SHIFT) - 1);
    int r0 = vr2.x >> VR_SHIFT;
    int v1 = vr2.y & ((1 << VR_SHIFT) - 1);
    int r1 = vr2.y >> VR_SHIFT;
    int n = t * 2;
    g_order[g_meta[v0].y + r0] = n;
    g_order[g_meta[v1].y + r1] = n + 1;
    // combined (ppos, vid) table, node-indexed, coalesced store
    float4 p0 = g_ppos4[v0];
    float4 p1 = g_ppos4[v1];
    p0.w = (float)v0;
    p1.w = (float)v1;
    g_ninfo[n]     = p0;
    g_ninfo[n + 1] = p1;
}

// ---------------- voxmax block body ----------------
__device__ __forceinline__ void vox_body(int vb, const float4* __restrict__ x4,
                                         float4* __restrict__ out4) {
    int t = vb * 256 + threadIdx.x;
    int w = t >> 5;
    int lane = t & 31;
    int2 meta = g_meta[w];
    int cnt = meta.x;
    float4 acc = make_float4(0.f, 0.f, 0.f, 0.f);
    if (cnt > 0) {
        const float NEG = -3.402823466e38f;
        acc = make_float4(NEG, NEG, NEG, NEG);
        int off = meta.y;
        int i = 0;
        for (; i + 4 <= cnt; i += 4) {
            int n0 = g_order[off + i + 0];
            int n1 = g_order[off + i + 1];
            int n2 = g_order[off + i + 2];
            int n3 = g_order[off + i + 3];
            float4 a = __ldcs(&x4[(size_t)n0 * 32 + lane]);
            float4 b = __ldcs(&x4[(size_t)n1 * 32 + lane]);
            float4 c = __ldcs(&x4[(size_t)n2 * 32 + lane]);
            float4 d = __ldcs(&x4[(size_t)n3 * 32 + lane]);
            acc.x = fmaxf(acc.x, fmaxf(fmaxf(a.x, b.x), fmaxf(c.x, d.x)));
            acc.y = fmaxf(acc.y, fmaxf(fmaxf(a.y, b.y), fmaxf(c.y, d.y)));
            acc.z = fmaxf(acc.z, fmaxf(fmaxf(a.z, b.z), fmaxf(c.z, d.z)));
            acc.w = fmaxf(acc.w, fmaxf(fmaxf(a.w, b.w), fmaxf(c.w, d.w)));
        }
        int rem = cnt - i;
        if (rem == 3) {
            int n0 = g_order[off + i + 0];
            int n1 = g_order[off + i + 1];
            int n2 = g_order[off + i + 2];
            float4 a = __ldcs(&x4[(size_t)n0 * 32 + lane]);
            float4 b = __ldcs(&x4[(size_t)n1 * 32 + lane]);
            float4 c = __ldcs(&x4[(size_t)n2 * 32 + lane]);
            acc.x = fmaxf(acc.x, fmaxf(fmaxf(a.x, b.x), c.x));
            acc.y = fmaxf(acc.y, fmaxf(fmaxf(a.y, b.y), c.y));
            acc.z = fmaxf(acc.z, fmaxf(fmaxf(a.z, b.z), c.z));
            acc.w = fmaxf(acc.w, fmaxf(fmaxf(a.w, b.w), c.w));
        } else if (rem == 2) {
            int n0 = g_order[off + i + 0];
            int n1 = g_order[off + i + 1];
            float4 a = __ldcs(&x4[(size_t)n0 * 32 + lane]);
            float4 b = __ldcs(&x4[(size_t)n1 * 32 + lane]);
            acc.x = fmaxf(acc.x, fmaxf(a.x, b.x));
            acc.y = fmaxf(acc.y, fmaxf(a.y, b.y));
            acc.z = fmaxf(acc.z, fmaxf(a.z, b.z));
            acc.w = fmaxf(acc.w, fmaxf(a.w, b.w));
        } else if (rem == 1) {
            int n0 = g_order[off + i];
            float4 a = __ldcs(&x4[(size_t)n0 * 32 + lane]);
            acc.x = fmaxf(acc.x, a.x);
            acc.y = fmaxf(acc.y, a.y);
            acc.z = fmaxf(acc.z, a.z);
            acc.w = fmaxf(acc.w, a.w);
        }
    }
    __stcs(&out4[(size_t)w * 32 + lane], acc);
}

// ---------------- edge block body: 4 edges/thread, 1-level gathers --------
__device__ __forceinline__ void edge_body(int eb, const void* __restrict__ ei_raw,
                                          float* __restrict__ out_f) {
    int t = eb * 256 + threadIdx.x;
    if (t >= E_EDGES / 4) return;

    int s0, s1, s2, s3, d0, d1, d2, d3;
    if (g_ei_is64) {
        const longlong2* p = (const longlong2*)ei_raw;
        longlong2 a = __ldcs(&p[2 * t]);
        longlong2 b = __ldcs(&p[2 * t + 1]);
        longlong2 c = __ldcs(&p[E_EDGES / 2 + 2 * t]);
        longlong2 d = __ldcs(&p[E_EDGES / 2 + 2 * t + 1]);
        s0 = (int)a.x; s1 = (int)a.y; s2 = (int)b.x; s3 = (int)b.y;
        d0 = (int)c.x; d1 = (int)c.y; d2 = (int)d.x; d3 = (int)d.y;
    } else {
        const int4* p = (const int4*)ei_raw;
        int4 a = __ldcs(&p[t]);
        int4 b = __ldcs(&p[E_EDGES / 4 + t]);
        s0 = a.x; s1 = a.y; s2 = a.z; s3 = a.w;
        d0 = b.x; d1 = b.y; d2 = b.z; d3 = b.w;
    }

    float o[12];
    float vsf[4], vdf[4], mk[4];

    // phase A: edges 0,1
    {
        float4 S0 = g_ninfo[s0], D0 = g_ninfo[d0];
        float4 S1 = g_ninfo[s1], D1 = g_ninfo[d1];
        bool m0 = S0.w != D0.w;
        bool m1 = S1.w != D1.w;
        vsf[0] = S0.w; vdf[0] = D0.w; mk[0] = m0 ? 1.f : 0.f;
        vsf[1] = S1.w; vdf[1] = D1.w; mk[1] = m1 ? 1.f : 0.f;
        o[0] = m0 ? (D0.x - S0.x) * INV_2R + 0.5f : 0.f;
        o[1] = m0 ? (D0.y - S0.y) * INV_2R + 0.5f : 0.f;
        o[2] = m0 ? (D0.z - S0.z) * INV_2R + 0.5f : 0.f;
        o[3] = m1 ? (D1.x - S1.x) * INV_2R + 0.5f : 0.f;
        o[4] = m1 ? (D1.y - S1.y) * INV_2R + 0.5f : 0.f;
        o[5] = m1 ? (D1.z - S1.z) * INV_2R + 0.5f : 0.f;
    }
    // phase B: edges 2,3
    {
        float4 S2 = g_ninfo[s2], D2 = g_ninfo[d2];
        float4 S3 = g_ninfo[s3], D3 = g_ninfo[d3];
        bool m2 = S2.w != D2.w;
        bool m3 = S3.w != D3.w;
        vsf[2] = S2.w; vdf[2] = D2.w; mk[2] = m2 ? 1.f : 0.f;
        vsf[3] = S3.w; vdf[3] = D3.w; mk[3] = m3 ? 1.f : 0.f;
        o[6]  = m2 ? (D2.x - S2.x) * INV_2R + 0.5f : 0.f;
        o[7]  = m2 ? (D2.y - S2.y) * INV_2R + 0.5f : 0.f;
        o[8]  = m2 ? (D2.z - S2.z) * INV_2R + 0.5f : 0.f;
        o[9]  = m3 ? (D3.x - S3.x) * INV_2R + 0.5f : 0.f;
        o[10] = m3 ? (D3.y - S3.y) * INV_2R + 0.5f : 0.f;
        o[11] = m3 ? (D3.z - S3.z) * INV_2R + 0.5f : 0.f;
    }

    __stcs(&((float4*)(out_f + OFF_EI))[t],
           make_float4(vsf[0], vsf[1], vsf[2], vsf[3]));
    __stcs(&((float4*)(out_f + OFF_EI + E_EDGES))[t],
           make_float4(vdf[0], vdf[1], vdf[2], vdf[3]));
    __stcs(&((float4*)(out_f + OFF_MASK))[t],
           make_float4(mk[0], mk[1], mk[2], mk[3]));

    float4* attr = (float4*)(out_f + OFF_ATTR + (size_t)t * 12);
    __stcs(&attr[0], make_float4(o[0], o[1], o[2], o[3]));
    __stcs(&attr[1], make_float4(o[4], o[5], o[6], o[7]));
    __stcs(&attr[2], make_float4(o[8], o[9], o[10], o[11]));
}

// ---------------- fat kernel: interleaved voxmax + edge blocks ----------------
__global__ void __launch_bounds__(256, 8)
k_voxedge(const float4* __restrict__ x4,
          const void* __restrict__ ei_raw,
          float* __restrict__ out_f) {
    if (blockIdx.x == 0 && threadIdx.x == 0) g_total = 0;  // reset for next launch
    int g = blockIdx.x / 5;
    int r = blockIdx.x % 5;
    if (r < 4) {
        vox_body(g * 4 + r, x4, (float4*)out_f);
    } else {
        if (g < EDGE_BLOCKS) edge_body(g, ei_raw, out_f);
    }
}

// ---------------- launch ----------------
extern "C" void kernel_launch(void* const* d_in, const int* in_sizes, int n_in,
                              void* d_out, int out_size) {
    const float* x = nullptr;
    const float* pos = nullptr;
    const int* batch = nullptr;
    const void* ei = nullptr;
    for (int i = 0; i < n_in; i++) {
        switch (in_sizes[i]) {
            case 64000000: x     = (const float*)d_in[i]; break;  // [N,F]
            case 1500000:  pos   = (const float*)d_in[i]; break;  // [N,3]
            case 500000:   batch = (const int*)d_in[i];   break;  // [N]
            case 8000000:  ei    = d_in[i];                break;  // [2,E]
        }
    }
    float* out = (float*)d_out;

    const int T = 256;
    k_node<<<(NODE_THREADS + T - 1) / T, T>>>((const float4*)pos,
                                              (const int4*)batch,
                                              (const int*)ei);
    k_alloc<<<V_SEG / 256, 256>>>(out);
    k_scatter<<<(SCAT_THREADS + T - 1) / T, T>>>();
    k_voxedge<<<FAT_BLOCKS, T>>>((const float4*)x, ei, out);
}